// round 9
// baseline (speedup 1.0000x reference)
#include <cuda_runtime.h>
#include <cuda_fp16.h>
#include <cstdint>

// channel_attention collapses to: out = LN_c(Wp @ x + bp)*gp + betap + x
// (softmax row-sum == 1 makes the q/k/attention branch an identity).
//
// HMMA m16n8k16 fp16 2-term X-split GEMM (y = Wh*Xh + Wh*Xl ~= Wh*x).
// W fragments pre-packed, held in registers. X staged raw fp32 via cp.async
// (double buffer) -> fp16 hi/lo smem; exact fp32 residual from raw buffer.
// 16 warps = 8 j-groups (16 j) x 2 s-halves (40 s) for latency hiding.

#define C        128
#define S        400
#define TS       80
#define NTILES   5
#define THREADS  512
#define RAWP     84                     // raw fp32 pitch (floats)
#define XPITCH   88                     // fp16 pitch (halves)
#define KSTEP    (16 * XPITCH * 2)

#define SM_RAW0  0
#define SM_RAW1  (128 * RAWP * 4)       // 43008
#define SM_XH    (2 * 128 * RAWP * 4)   // 86016
#define SM_XL    (SM_XH + 128 * XPITCH * 2)   // 108544
#define SM_BP    (SM_XL + 128 * XPITCH * 2)   // 131072
#define SM_GP    (SM_BP + 512)
#define SM_BT    (SM_GP + 512)
#define SM_RED   (SM_BT + 512)          // float2[8][80]
#define SM_TOTAL (SM_RED + 5120)        // 137728 B

// Wh fragments in mma order: [mt 8][ks 8][lane 32] x uint4
__device__ __align__(16) uint32_t Whf[8 * 8 * 32 * 4];

__device__ __forceinline__ uint32_t smem_u32(const void* p) {
    uint32_t a;
    asm("{ .reg .u64 t; cvta.to.shared.u64 t, %1; cvt.u32.u64 %0, t; }"
        : "=r"(a) : "l"(p));
    return a;
}
__device__ __forceinline__ void cp16(uint32_t dst, const void* src) {
    asm volatile("cp.async.cg.shared.global [%0], [%1], 16;"
                 :: "r"(dst), "l"(src));
}
__device__ __forceinline__ void cp_commit() {
    asm volatile("cp.async.commit_group;");
}
__device__ __forceinline__ void cp_wait0() {
    asm volatile("cp.async.wait_group 0;");
}
__device__ __forceinline__ void ldsm4t(uint32_t* r, uint32_t addr) {
    asm volatile("ldmatrix.sync.aligned.m8n8.x4.trans.shared.b16 {%0,%1,%2,%3}, [%4];"
                 : "=r"(r[0]), "=r"(r[1]), "=r"(r[2]), "=r"(r[3]) : "r"(addr));
}
__device__ __forceinline__ void ldsm2t(uint32_t* r, uint32_t addr) {
    asm volatile("ldmatrix.sync.aligned.m8n8.x2.trans.shared.b16 {%0,%1}, [%2];"
                 : "=r"(r[0]), "=r"(r[1]) : "r"(addr));
}
__device__ __forceinline__ void mma16816(float d[4], uint4 a,
                                         uint32_t b0, uint32_t b1) {
    asm volatile(
        "mma.sync.aligned.m16n8k16.row.col.f32.f16.f16.f32 "
        "{%0,%1,%2,%3}, {%4,%5,%6,%7}, {%8,%9}, {%0,%1,%2,%3};"
        : "+f"(d[0]), "+f"(d[1]), "+f"(d[2]), "+f"(d[3])
        : "r"(a.x), "r"(a.y), "r"(a.z), "r"(a.w), "r"(b0), "r"(b1));
}
__device__ __forceinline__ uint32_t pk_h2(float a, float b) {
    __half2 h = __floats2half2_rn(a, b);    // low = a
    return *reinterpret_cast<uint32_t*>(&h);
}

// pack Wh into mma A-fragment order (mt = 16-j tile index 0..7)
__global__ void wprep(const float* __restrict__ Wp) {
    int idx  = blockIdx.x * 256 + threadIdx.x;   // (mt*8+ks)*32+lane
    int lane = idx & 31;
    int ks   = (idx >> 5) & 7;
    int mt   = idx >> 8;
    uint32_t h4[4];
    #pragma unroll
    for (int r = 0; r < 4; r++) {
        int j = mt * 16 + (r & 1) * 8 + (lane >> 2);
        int c = ks * 16 + (r >> 1) * 8 + 2 * (lane & 3);
        h4[r] = pk_h2(Wp[j * C + c], Wp[j * C + c + 1]);
    }
    ((uint4*)Whf)[idx] = make_uint4(h4[0], h4[1], h4[2], h4[3]);
}

extern __shared__ char smem[];

__global__ __launch_bounds__(THREADS, 1)
void ca_mma(const float* __restrict__ x,
            const float* __restrict__ bp,
            const float* __restrict__ gp,
            const float* __restrict__ betap,
            float* __restrict__ out) {
    const int tid  = threadIdx.x;
    const int warp = tid >> 5;
    const int lane = tid & 31;
    const int jg   = warp >> 1;          // 0..7 : 16-j group
    const int sh   = warp & 1;           // 0..1 : 40-s half
    const int g    = lane >> 2;
    const int t4   = lane & 3;
    const int bo   = blockIdx.x;

    const float* xg = x   + (size_t)bo * C * S;
    float*       ob = out + (size_t)bo * C * S;

    float*  sbp = (float*)(smem + SM_BP);
    float*  sgp = (float*)(smem + SM_GP);
    float*  sbt = (float*)(smem + SM_BT);
    float2* red = (float2*)(smem + SM_RED);

    if (tid < C) {
        sbp[tid] = bp[tid];
        sgp[tid] = gp[tid];
        sbt[tid] = betap[tid];
    }

    // ---- Wh fragments: one 16-j tile per warp, held in registers ----
    uint4 Ah[8];
    {
        const uint4* wh = (const uint4*)Whf;
        #pragma unroll
        for (int ks = 0; ks < 8; ks++)
            Ah[ks] = wh[(jg * 8 + ks) * 32 + lane];
    }

    // ---- per-thread X chunk map: 5 x 16B over [128c][80s] ----
    int soff[5], goff[5];
    #pragma unroll
    for (int k = 0; k < 5; k++) {
        int idx = tid + k * THREADS;
        int c = idx / 20;
        int q = (idx % 20) * 4;
        soff[k] = c * RAWP + q;
        goff[k] = c * S + q;
    }

    const int lr = lane & 15;
    const int lc = (lane >> 4) << 3;
    const int sb = sh * 40;
    const uint32_t s0   = smem_u32(smem);
    const uint32_t xrel = (uint32_t)((lr * XPITCH + sb + lc) * 2);
    const uint32_t aXh  = s0 + SM_XH + xrel;
    const uint32_t aXl  = s0 + SM_XL + xrel;
    __half* xh = (__half*)(smem + SM_XH);
    __half* xl = (__half*)(smem + SM_XL);

    // ---- prologue: stage + convert tile 0 ----
    #pragma unroll
    for (int k = 0; k < 5; k++)
        cp16(s0 + SM_RAW0 + soff[k] * 4, xg + goff[k]);
    cp_commit();
    cp_wait0();
    __syncthreads();
    {
        const float* rw = (const float*)(smem + SM_RAW0);
        #pragma unroll
        for (int k = 0; k < 5; k++) {
            float4 v = *(const float4*)(rw + soff[k]);
            __half h0 = __float2half_rn(v.x);
            __half h1 = __float2half_rn(v.y);
            __half h2 = __float2half_rn(v.z);
            __half h3 = __float2half_rn(v.w);
            int c = soff[k] / RAWP;
            int q = soff[k] % RAWP;
            int o = c * XPITCH + q;
            *(uint2*)(xh + o) = make_uint2(pk_h2(v.x, v.y), pk_h2(v.z, v.w));
            *(uint2*)(xl + o) = make_uint2(
                pk_h2(v.x - __half2float(h0), v.y - __half2float(h1)),
                pk_h2(v.z - __half2float(h2), v.w - __half2float(h3)));
        }
    }
    __syncthreads();

    for (int t = 0; t < NTILES; t++) {
        // stage next tile while computing this one
        if (t + 1 < NTILES) {
            const float* nx = xg + (t + 1) * TS;
            uint32_t dst = s0 + (((t + 1) & 1) ? SM_RAW1 : SM_RAW0);
            #pragma unroll
            for (int k = 0; k < 5; k++)
                cp16(dst + soff[k] * 4, nx + goff[k]);
            cp_commit();
        }

        // ---- MMA: A in regs, B = Xh, Xl via ldsm ----
        float d[5][4];
        #pragma unroll
        for (int n = 0; n < 5; n++)
            #pragma unroll
            for (int i = 0; i < 4; i++) d[n][i] = 0.0f;

        #pragma unroll
        for (int ks = 0; ks < 8; ks++) {
            uint32_t bh[10], bl[10];
            ldsm4t(bh,     aXh + ks * KSTEP);
            ldsm4t(bh + 4, aXh + ks * KSTEP + 32);
            ldsm2t(bh + 8, aXh + ks * KSTEP + 64);
            ldsm4t(bl,     aXl + ks * KSTEP);
            ldsm4t(bl + 4, aXl + ks * KSTEP + 32);
            ldsm2t(bl + 8, aXl + ks * KSTEP + 64);
            uint4 ah = Ah[ks];
            #pragma unroll
            for (int n = 0; n < 5; n++) {
                mma16816(d[n], ah, bh[2 * n], bh[2 * n + 1]);
                mma16816(d[n], ah, bl[2 * n], bl[2 * n + 1]);
            }
        }

        // ---- epilogue: +bias, LN partials over 16 j in-warp ----
        const int j0 = jg * 16 + g;
        const int j1 = j0 + 8;
        {
            float b0 = sbp[j0], b1 = sbp[j1];
            #pragma unroll
            for (int n = 0; n < 5; n++) {
                d[n][0] += b0;
                d[n][1] += b0;
                d[n][2] += b1;
                d[n][3] += b1;
            }
        }
        float sum[5][2], sq[5][2];
        #pragma unroll
        for (int n = 0; n < 5; n++) {
            sum[n][0] = d[n][0] + d[n][2];
            sum[n][1] = d[n][1] + d[n][3];
            sq[n][0] = fmaf(d[n][0], d[n][0], d[n][2] * d[n][2]);
            sq[n][1] = fmaf(d[n][1], d[n][1], d[n][3] * d[n][3]);
        }
        #pragma unroll
        for (int off = 4; off <= 16; off <<= 1) {
            #pragma unroll
            for (int n = 0; n < 5; n++) {
                #pragma unroll
                for (int p = 0; p < 2; p++) {
                    sum[n][p] += __shfl_xor_sync(0xffffffffu, sum[n][p], off);
                    sq[n][p]  += __shfl_xor_sync(0xffffffffu, sq[n][p],  off);
                }
            }
        }
        if (lane < 4) {
            #pragma unroll
            for (int n = 0; n < 5; n++)
                #pragma unroll
                for (int p = 0; p < 2; p++)
                    red[jg * TS + sb + n * 8 + 2 * lane + p] =
                        make_float2(sum[n][p], sq[n][p]);
        }
        __syncthreads();

        float mu[5][2], rs[5][2];
        #pragma unroll
        for (int n = 0; n < 5; n++) {
            #pragma unroll
            for (int p = 0; p < 2; p++) {
                int col = sb + n * 8 + 2 * t4 + p;
                float sv = 0.f, qv = 0.f;
                #pragma unroll
                for (int jj = 0; jj < 8; jj++) {
                    float2 r = red[jj * TS + col];
                    sv += r.x;
                    qv += r.y;
                }
                float m_  = sv * (1.0f / 128.0f);
                float var = qv * (1.0f / 128.0f) - m_ * m_;
                mu[n][p] = m_;
                rs[n][p] = rsqrtf(var + 1e-5f);
            }
        }

        // ---- apply LN + exact fp32 residual from raw buffer, store ----
        const int tb = t * TS;
        const float* rw = (const float*)(smem + ((t & 1) ? SM_RAW1 : SM_RAW0));
        {
            float g0 = sgp[j0], e0 = sbt[j0];
            float g1 = sgp[j1], e1 = sbt[j1];
            #pragma unroll
            for (int n = 0; n < 5; n++) {
                int sl = sb + n * 8 + 2 * t4;
                float2 x0 = *(const float2*)(rw + j0 * RAWP + sl);
                float2 x1 = *(const float2*)(rw + j1 * RAWP + sl);
                float2 o0, o1;
                o0.x = (d[n][0] - mu[n][0]) * rs[n][0] * g0 + e0 + x0.x;
                o0.y = (d[n][1] - mu[n][1]) * rs[n][1] * g0 + e0 + x0.y;
                o1.x = (d[n][2] - mu[n][0]) * rs[n][0] * g1 + e1 + x1.x;
                o1.y = (d[n][3] - mu[n][1]) * rs[n][1] * g1 + e1 + x1.y;
                *(float2*)(ob + (size_t)j0 * S + tb + sl) = o0;
                *(float2*)(ob + (size_t)j1 * S + tb + sl) = o1;
            }
        }

        // ---- finish staging, convert next tile ----
        cp_wait0();
        __syncthreads();
        if (t + 1 < NTILES) {
            const float* rn =
                (const float*)(smem + (((t + 1) & 1) ? SM_RAW1 : SM_RAW0));
            #pragma unroll
            for (int k = 0; k < 5; k++) {
                float4 v = *(const float4*)(rn + soff[k]);
                __half h0 = __float2half_rn(v.x);
                __half h1 = __float2half_rn(v.y);
                __half h2 = __float2half_rn(v.z);
                __half h3 = __float2half_rn(v.w);
                int c = soff[k] / RAWP;
                int q = soff[k] % RAWP;
                int o = c * XPITCH + q;
                *(uint2*)(xh + o) = make_uint2(pk_h2(v.x, v.y), pk_h2(v.z, v.w));
                *(uint2*)(xl + o) = make_uint2(
                    pk_h2(v.x - __half2float(h0), v.y - __half2float(h1)),
                    pk_h2(v.z - __half2float(h2), v.w - __half2float(h3)));
            }
        }
        __syncthreads();
    }
}

extern "C" void kernel_launch(void* const* d_in, const int* in_sizes, int n_in,
                              void* d_out, int out_size) {
    // metadata order: x, Wq, bq, gq, betaq, Wk, bk, gk, betak, Wp, bp, gp, betap
    const float* x     = (const float*)d_in[0];
    const float* Wp    = (const float*)d_in[9];
    const float* bp    = (const float*)d_in[10];
    const float* gp    = (const float*)d_in[11];
    const float* betap = (const float*)d_in[12];
    float* out = (float*)d_out;

    const int BO = in_sizes[0] / (C * S);   // 1024

    cudaFuncSetAttribute(ca_mma, cudaFuncAttributeMaxDynamicSharedMemorySize,
                         SM_TOTAL);

    wprep<<<8, 256>>>(Wp);
    ca_mma<<<BO, THREADS, SM_TOTAL>>>(x, bp, gp, betap, out);
}

// round 10
// speedup vs baseline: 1.4136x; 1.4136x over previous
#include <cuda_runtime.h>
#include <cuda_fp16.h>
#include <cstdint>

// channel_attention collapses to: out = LN_c(Wp @ x + bp)*gp + betap + x
// (softmax row-sum == 1 makes the q/k/attention branch an identity).
//
// HMMA m16n8k16 fp16 2-term X-split GEMM (y = Wh*Xh + Wh*Xl ~= Wh*x).
// 8 warps = 4 j-groups x 2 s-halves; A fragments streamed from an L1-resident
// pre-packed global image (no A regs); X staged raw fp32 via cp.async into a
// single buffer, converted to fp16 hi/lo; residual reconstructed as hi+lo.
// smem ~90 KB + <=128 regs -> 2 CTAs/SM for latency hiding.

#define C        128
#define S        400
#define TS       80
#define NTILES   5
#define THREADS  256
#define RAWP     84                     // raw fp32 pitch (floats)
#define XPITCH   88                     // fp16 pitch (halves)
#define KSTEP    (16 * XPITCH * 2)

#define SM_RAW   0                      // 128*84*4 = 43008
#define SM_XH    43008                  // 128*88*2 = 22528
#define SM_XL    65536
#define SM_BP    88064
#define SM_GP    (SM_BP + 512)
#define SM_BT    (SM_GP + 512)
#define SM_RED   (SM_BT + 512)          // float2[4][80] = 2560
#define SM_TOTAL (SM_RED + 2560)        // 92160 B -> 2 CTAs/SM

// Wh fragments in mma order: [mt 8][ks 8][lane 32] x uint4 (16 KB, L1-hot)
__device__ __align__(16) uint32_t Whf[8 * 8 * 32 * 4];

__device__ __forceinline__ uint32_t smem_u32(const void* p) {
    uint32_t a;
    asm("{ .reg .u64 t; cvta.to.shared.u64 t, %1; cvt.u32.u64 %0, t; }"
        : "=r"(a) : "l"(p));
    return a;
}
__device__ __forceinline__ void cp16(uint32_t dst, const void* src) {
    asm volatile("cp.async.cg.shared.global [%0], [%1], 16;"
                 :: "r"(dst), "l"(src));
}
__device__ __forceinline__ void cp_commit() {
    asm volatile("cp.async.commit_group;");
}
__device__ __forceinline__ void cp_wait0() {
    asm volatile("cp.async.wait_group 0;");
}
__device__ __forceinline__ void ldsm4t(uint32_t* r, uint32_t addr) {
    asm volatile("ldmatrix.sync.aligned.m8n8.x4.trans.shared.b16 {%0,%1,%2,%3}, [%4];"
                 : "=r"(r[0]), "=r"(r[1]), "=r"(r[2]), "=r"(r[3]) : "r"(addr));
}
__device__ __forceinline__ void ldsm2t(uint32_t* r, uint32_t addr) {
    asm volatile("ldmatrix.sync.aligned.m8n8.x2.trans.shared.b16 {%0,%1}, [%2];"
                 : "=r"(r[0]), "=r"(r[1]) : "r"(addr));
}
__device__ __forceinline__ void mma16816(float d[4], uint4 a,
                                         uint32_t b0, uint32_t b1) {
    asm volatile(
        "mma.sync.aligned.m16n8k16.row.col.f32.f16.f16.f32 "
        "{%0,%1,%2,%3}, {%4,%5,%6,%7}, {%8,%9}, {%0,%1,%2,%3};"
        : "+f"(d[0]), "+f"(d[1]), "+f"(d[2]), "+f"(d[3])
        : "r"(a.x), "r"(a.y), "r"(a.z), "r"(a.w), "r"(b0), "r"(b1));
}
__device__ __forceinline__ uint32_t pk_h2(float a, float b) {
    __half2 h = __floats2half2_rn(a, b);    // low = a
    return *reinterpret_cast<uint32_t*>(&h);
}

// pack Wh into mma A-fragment order (mt = 16-j tile index 0..7)
__global__ void wprep(const float* __restrict__ Wp) {
    int idx  = blockIdx.x * 256 + threadIdx.x;   // (mt*8+ks)*32+lane
    int lane = idx & 31;
    int ks   = (idx >> 5) & 7;
    int mt   = idx >> 8;
    uint32_t h4[4];
    #pragma unroll
    for (int r = 0; r < 4; r++) {
        int j = mt * 16 + (r & 1) * 8 + (lane >> 2);
        int c = ks * 16 + (r >> 1) * 8 + 2 * (lane & 3);
        h4[r] = pk_h2(Wp[j * C + c], Wp[j * C + c + 1]);
    }
    ((uint4*)Whf)[idx] = make_uint4(h4[0], h4[1], h4[2], h4[3]);
}

extern __shared__ char smem[];

__device__ __forceinline__ void convert_raw(int tid, const float* rw,
                                            __half* xh, __half* xl) {
    #pragma unroll
    for (int k = 0; k < 10; k++) {
        int idx = tid + k * THREADS;
        int c = idx / 20;
        int q = (idx % 20) * 4;
        float4 v = *(const float4*)(rw + c * RAWP + q);
        __half h0 = __float2half_rn(v.x);
        __half h1 = __float2half_rn(v.y);
        __half h2 = __float2half_rn(v.z);
        __half h3 = __float2half_rn(v.w);
        int o = c * XPITCH + q;
        *(uint2*)(xh + o) = make_uint2(pk_h2(v.x, v.y), pk_h2(v.z, v.w));
        *(uint2*)(xl + o) = make_uint2(
            pk_h2(v.x - __half2float(h0), v.y - __half2float(h1)),
            pk_h2(v.z - __half2float(h2), v.w - __half2float(h3)));
    }
}

__global__ __launch_bounds__(THREADS, 2)
void ca_mma(const float* __restrict__ x,
            const float* __restrict__ bp,
            const float* __restrict__ gp,
            const float* __restrict__ betap,
            float* __restrict__ out) {
    const int tid  = threadIdx.x;
    const int warp = tid >> 5;
    const int lane = tid & 31;
    const int jg   = warp >> 1;          // 0..3 : 32-j group
    const int sh   = warp & 1;           // 0..1 : 40-s half
    const int g    = lane >> 2;
    const int t4   = lane & 3;
    const int bo   = blockIdx.x;

    const float* xg = x   + (size_t)bo * C * S;
    float*       ob = out + (size_t)bo * C * S;

    float*  sbp = (float*)(smem + SM_BP);
    float*  sgp = (float*)(smem + SM_GP);
    float*  sbt = (float*)(smem + SM_BT);
    float2* red = (float2*)(smem + SM_RED);
    __half* xh  = (__half*)(smem + SM_XH);
    __half* xl  = (__half*)(smem + SM_XL);
    const float* rw = (const float*)(smem + SM_RAW);

    if (tid < C) {
        sbp[tid] = bp[tid];
        sgp[tid] = gp[tid];
        sbt[tid] = betap[tid];
    }

    const int lr = lane & 15;
    const int lc = (lane >> 4) << 3;
    const int sb = sh * 40;
    const uint32_t s0   = smem_u32(smem);
    const uint32_t xrel = (uint32_t)((lr * XPITCH + sb + lc) * 2);
    const uint32_t aXh  = s0 + SM_XH + xrel;
    const uint32_t aXl  = s0 + SM_XL + xrel;
    const uint4* wh = (const uint4*)Whf;

    // ---- prologue: stage + convert tile 0 ----
    #pragma unroll
    for (int k = 0; k < 10; k++) {
        int idx = tid + k * THREADS;
        int c = idx / 20;
        int q = (idx % 20) * 4;
        cp16(s0 + SM_RAW + (c * RAWP + q) * 4, xg + (size_t)c * S + q);
    }
    cp_commit();
    cp_wait0();
    __syncthreads();
    convert_raw(tid, rw, xh, xl);
    __syncthreads();

    for (int t = 0; t < NTILES; t++) {
        // stage next tile into RAW while computing from XH/XL
        if (t + 1 < NTILES) {
            const float* nx = xg + (t + 1) * TS;
            #pragma unroll
            for (int k = 0; k < 10; k++) {
                int idx = tid + k * THREADS;
                int c = idx / 20;
                int q = (idx % 20) * 4;
                cp16(s0 + SM_RAW + (c * RAWP + q) * 4, nx + (size_t)c * S + q);
            }
            cp_commit();
        }

        // ---- MMA: A streamed from global (L1-hot), B via ldsm ----
        float d[2][5][4];
        #pragma unroll
        for (int mt = 0; mt < 2; mt++)
            #pragma unroll
            for (int n = 0; n < 5; n++)
                #pragma unroll
                for (int i = 0; i < 4; i++) d[mt][n][i] = 0.0f;

        #pragma unroll
        for (int ks = 0; ks < 8; ks++) {
            uint4 ah0 = __ldg(wh + ((2 * jg)     * 8 + ks) * 32 + lane);
            uint4 ah1 = __ldg(wh + ((2 * jg + 1) * 8 + ks) * 32 + lane);
            uint32_t bh[10], bl[10];
            ldsm4t(bh,     aXh + ks * KSTEP);
            ldsm4t(bh + 4, aXh + ks * KSTEP + 32);
            ldsm2t(bh + 8, aXh + ks * KSTEP + 64);
            ldsm4t(bl,     aXl + ks * KSTEP);
            ldsm4t(bl + 4, aXl + ks * KSTEP + 32);
            ldsm2t(bl + 8, aXl + ks * KSTEP + 64);
            #pragma unroll
            for (int n = 0; n < 5; n++) {
                mma16816(d[0][n], ah0, bh[2 * n], bh[2 * n + 1]);
                mma16816(d[0][n], ah0, bl[2 * n], bl[2 * n + 1]);
                mma16816(d[1][n], ah1, bh[2 * n], bh[2 * n + 1]);
                mma16816(d[1][n], ah1, bl[2 * n], bl[2 * n + 1]);
            }
        }

        // ---- epilogue: +bias, LN stats over 32 j in-warp + 4-group combine ----
        float sum[5][2], sq[5][2];
        #pragma unroll
        for (int n = 0; n < 5; n++)
            #pragma unroll
            for (int p = 0; p < 2; p++) { sum[n][p] = 0.f; sq[n][p] = 0.f; }

        #pragma unroll
        for (int mt = 0; mt < 2; mt++) {
            int j0 = jg * 32 + mt * 16 + g;
            float b0 = sbp[j0], b1 = sbp[j0 + 8];
            #pragma unroll
            for (int n = 0; n < 5; n++) {
                d[mt][n][0] += b0;
                d[mt][n][1] += b0;
                d[mt][n][2] += b1;
                d[mt][n][3] += b1;
                sum[n][0] += d[mt][n][0] + d[mt][n][2];
                sum[n][1] += d[mt][n][1] + d[mt][n][3];
                sq[n][0] = fmaf(d[mt][n][0], d[mt][n][0],
                           fmaf(d[mt][n][2], d[mt][n][2], sq[n][0]));
                sq[n][1] = fmaf(d[mt][n][1], d[mt][n][1],
                           fmaf(d[mt][n][3], d[mt][n][3], sq[n][1]));
            }
        }
        #pragma unroll
        for (int off = 4; off <= 16; off <<= 1) {
            #pragma unroll
            for (int n = 0; n < 5; n++) {
                #pragma unroll
                for (int p = 0; p < 2; p++) {
                    sum[n][p] += __shfl_xor_sync(0xffffffffu, sum[n][p], off);
                    sq[n][p]  += __shfl_xor_sync(0xffffffffu, sq[n][p],  off);
                }
            }
        }
        if (lane < 4) {
            #pragma unroll
            for (int n = 0; n < 5; n++)
                #pragma unroll
                for (int p = 0; p < 2; p++)
                    red[jg * TS + sb + n * 8 + 2 * lane + p] =
                        make_float2(sum[n][p], sq[n][p]);
        }
        __syncthreads();

        float mu[5][2], rs[5][2];
        #pragma unroll
        for (int n = 0; n < 5; n++) {
            #pragma unroll
            for (int p = 0; p < 2; p++) {
                int col = sb + n * 8 + 2 * t4 + p;
                float sv = 0.f, qv = 0.f;
                #pragma unroll
                for (int jj = 0; jj < 4; jj++) {
                    float2 r = red[jj * TS + col];
                    sv += r.x;
                    qv += r.y;
                }
                float m_  = sv * (1.0f / 128.0f);
                float var = qv * (1.0f / 128.0f) - m_ * m_;
                mu[n][p] = m_;
                rs[n][p] = rsqrtf(var + 1e-5f);
            }
        }

        // ---- apply LN + residual (x = hi + lo), store ----
        const int tb = t * TS;
        #pragma unroll
        for (int mt = 0; mt < 2; mt++) {
            int j0 = jg * 32 + mt * 16 + g;
            int j1 = j0 + 8;
            float g0 = sgp[j0], e0 = sbt[j0];
            float g1 = sgp[j1], e1 = sbt[j1];
            #pragma unroll
            for (int n = 0; n < 5; n++) {
                int sl = sb + n * 8 + 2 * t4;
                __half2 h0 = *(__half2*)(xh + j0 * XPITCH + sl);
                __half2 l0 = *(__half2*)(xl + j0 * XPITCH + sl);
                __half2 h1 = *(__half2*)(xh + j1 * XPITCH + sl);
                __half2 l1 = *(__half2*)(xl + j1 * XPITCH + sl);
                float2 o0, o1;
                o0.x = (d[mt][n][0] - mu[n][0]) * rs[n][0] * g0 + e0 +
                       __half2float(h0.x) + __half2float(l0.x);
                o0.y = (d[mt][n][1] - mu[n][1]) * rs[n][1] * g0 + e0 +
                       __half2float(h0.y) + __half2float(l0.y);
                o1.x = (d[mt][n][2] - mu[n][0]) * rs[n][0] * g1 + e1 +
                       __half2float(h1.x) + __half2float(l1.x);
                o1.y = (d[mt][n][3] - mu[n][1]) * rs[n][1] * g1 + e1 +
                       __half2float(h1.y) + __half2float(l1.y);
                *(float2*)(ob + (size_t)j0 * S + tb + sl) = o0;
                *(float2*)(ob + (size_t)j1 * S + tb + sl) = o1;
            }
        }

        // ---- next tile ready in RAW; convert into XH/XL ----
        if (t + 1 < NTILES) {
            cp_wait0();
            __syncthreads();      // everyone done reading XH/XL; RAW landed
            convert_raw(tid, rw, xh, xl);
            __syncthreads();
        }
    }
}

extern "C" void kernel_launch(void* const* d_in, const int* in_sizes, int n_in,
                              void* d_out, int out_size) {
    // metadata order: x, Wq, bq, gq, betaq, Wk, bk, gk, betak, Wp, bp, gp, betap
    const float* x     = (const float*)d_in[0];
    const float* Wp    = (const float*)d_in[9];
    const float* bp    = (const float*)d_in[10];
    const float* gp    = (const float*)d_in[11];
    const float* betap = (const float*)d_in[12];
    float* out = (float*)d_out;

    const int BO = in_sizes[0] / (C * S);   // 1024

    cudaFuncSetAttribute(ca_mma, cudaFuncAttributeMaxDynamicSharedMemorySize,
                         SM_TOTAL);

    wprep<<<8, 256>>>(Wp);
    ca_mma<<<BO, THREADS, SM_TOTAL>>>(x, bp, gp, betap, out);
}

// round 11
// speedup vs baseline: 1.5614x; 1.1046x over previous
#include <cuda_runtime.h>
#include <cuda_fp16.h>
#include <cstdint>

// channel_attention collapses to: out = LN_c(Wp @ x + bp)*gp + betap + x
// (softmax row-sum == 1 makes the q/k/attention branch an identity).
//
// HMMA m16n8k16 fp16 single-term GEMM: y = Wh*Xh (both fp16-rounded;
// rel_err ~2e-4 << 1e-3). Residual x stays EXACT: read from the raw fp32
// staging buffer (double-buffered via cp.async). 8 warps = 4 j-groups x
// 2 s-halves; A fragments streamed from an L1-hot pre-packed global image.
// ~110 KB smem + 128 regs -> 2 CTAs/SM.

#define C        128
#define S        400
#define TS       80
#define NTILES   5
#define THREADS  256
#define RAWP     84                     // raw fp32 pitch (floats)
#define XPITCH   88                     // fp16 pitch (halves)
#define KSTEP    (16 * XPITCH * 2)

#define SM_RAW0  0                      // 128*84*4 = 43008
#define SM_RAW1  43008
#define SM_XH    86016                  // 128*88*2 = 22528
#define SM_BP    108544
#define SM_GP    (SM_BP + 512)
#define SM_BT    (SM_GP + 512)
#define SM_RED   (SM_BT + 512)          // float2[4][80] = 2560
#define SM_TOTAL (SM_RED + 2560)        // 112640 B -> 2 CTAs/SM

// Wh fragments in mma order: [mt 8][ks 8][lane 32] x uint4 (16 KB, L1-hot)
__device__ __align__(16) uint32_t Whf[8 * 8 * 32 * 4];

__device__ __forceinline__ uint32_t smem_u32(const void* p) {
    uint32_t a;
    asm("{ .reg .u64 t; cvta.to.shared.u64 t, %1; cvt.u32.u64 %0, t; }"
        : "=r"(a) : "l"(p));
    return a;
}
__device__ __forceinline__ void cp16(uint32_t dst, const void* src) {
    asm volatile("cp.async.cg.shared.global [%0], [%1], 16;"
                 :: "r"(dst), "l"(src));
}
__device__ __forceinline__ void cp_commit() {
    asm volatile("cp.async.commit_group;");
}
__device__ __forceinline__ void cp_wait0() {
    asm volatile("cp.async.wait_group 0;");
}
__device__ __forceinline__ void ldsm4t(uint32_t* r, uint32_t addr) {
    asm volatile("ldmatrix.sync.aligned.m8n8.x4.trans.shared.b16 {%0,%1,%2,%3}, [%4];"
                 : "=r"(r[0]), "=r"(r[1]), "=r"(r[2]), "=r"(r[3]) : "r"(addr));
}
__device__ __forceinline__ void ldsm2t(uint32_t* r, uint32_t addr) {
    asm volatile("ldmatrix.sync.aligned.m8n8.x2.trans.shared.b16 {%0,%1}, [%2];"
                 : "=r"(r[0]), "=r"(r[1]) : "r"(addr));
}
__device__ __forceinline__ void mma16816(float d[4], uint4 a,
                                         uint32_t b0, uint32_t b1) {
    asm volatile(
        "mma.sync.aligned.m16n8k16.row.col.f32.f16.f16.f32 "
        "{%0,%1,%2,%3}, {%4,%5,%6,%7}, {%8,%9}, {%0,%1,%2,%3};"
        : "+f"(d[0]), "+f"(d[1]), "+f"(d[2]), "+f"(d[3])
        : "r"(a.x), "r"(a.y), "r"(a.z), "r"(a.w), "r"(b0), "r"(b1));
}
__device__ __forceinline__ uint32_t pk_h2(float a, float b) {
    __half2 h = __floats2half2_rn(a, b);    // low = a
    return *reinterpret_cast<uint32_t*>(&h);
}

// pack Wh into mma A-fragment order (mt = 16-j tile index 0..7)
__global__ void wprep(const float* __restrict__ Wp) {
    int idx  = blockIdx.x * 256 + threadIdx.x;   // (mt*8+ks)*32+lane
    int lane = idx & 31;
    int ks   = (idx >> 5) & 7;
    int mt   = idx >> 8;
    uint32_t h4[4];
    #pragma unroll
    for (int r = 0; r < 4; r++) {
        int j = mt * 16 + (r & 1) * 8 + (lane >> 2);
        int c = ks * 16 + (r >> 1) * 8 + 2 * (lane & 3);
        h4[r] = pk_h2(Wp[j * C + c], Wp[j * C + c + 1]);
    }
    ((uint4*)Whf)[idx] = make_uint4(h4[0], h4[1], h4[2], h4[3]);
}

extern __shared__ char smem[];

__device__ __forceinline__ void convert_raw(int tid, const float* rw,
                                            __half* xh) {
    #pragma unroll
    for (int k = 0; k < 10; k++) {
        int idx = tid + k * THREADS;
        int c = idx / 20;
        int q = (idx % 20) * 4;
        float4 v = *(const float4*)(rw + c * RAWP + q);
        int o = c * XPITCH + q;
        *(uint2*)(xh + o) = make_uint2(pk_h2(v.x, v.y), pk_h2(v.z, v.w));
    }
}

__global__ __launch_bounds__(THREADS, 2)
void ca_mma(const float* __restrict__ x,
            const float* __restrict__ bp,
            const float* __restrict__ gp,
            const float* __restrict__ betap,
            float* __restrict__ out) {
    const int tid  = threadIdx.x;
    const int warp = tid >> 5;
    const int lane = tid & 31;
    const int jg   = warp >> 1;          // 0..3 : 32-j group
    const int sh   = warp & 1;           // 0..1 : 40-s half
    const int g    = lane >> 2;
    const int t4   = lane & 3;
    const int bo   = blockIdx.x;

    const float* xg = x   + (size_t)bo * C * S;
    float*       ob = out + (size_t)bo * C * S;

    float*  sbp = (float*)(smem + SM_BP);
    float*  sgp = (float*)(smem + SM_GP);
    float*  sbt = (float*)(smem + SM_BT);
    float2* red = (float2*)(smem + SM_RED);
    __half* xh  = (__half*)(smem + SM_XH);

    if (tid < C) {
        sbp[tid] = bp[tid];
        sgp[tid] = gp[tid];
        sbt[tid] = betap[tid];
    }

    const int lr = lane & 15;
    const int lc = (lane >> 4) << 3;
    const int sb = sh * 40;
    const uint32_t s0   = smem_u32(smem);
    const uint32_t aXh  = s0 + SM_XH + (uint32_t)((lr * XPITCH + sb + lc) * 2);
    const uint4* wh = (const uint4*)Whf;

    // ---- prologue: stage + convert tile 0 ----
    #pragma unroll
    for (int k = 0; k < 10; k++) {
        int idx = tid + k * THREADS;
        int c = idx / 20;
        int q = (idx % 20) * 4;
        cp16(s0 + SM_RAW0 + (c * RAWP + q) * 4, xg + (size_t)c * S + q);
    }
    cp_commit();
    cp_wait0();
    __syncthreads();
    convert_raw(tid, (const float*)(smem + SM_RAW0), xh);
    __syncthreads();

    for (int t = 0; t < NTILES; t++) {
        // stage next tile into the other RAW buffer (overlaps compute)
        if (t + 1 < NTILES) {
            const float* nx = xg + (t + 1) * TS;
            uint32_t dst = s0 + (((t + 1) & 1) ? SM_RAW1 : SM_RAW0);
            #pragma unroll
            for (int k = 0; k < 10; k++) {
                int idx = tid + k * THREADS;
                int c = idx / 20;
                int q = (idx % 20) * 4;
                cp16(dst + (c * RAWP + q) * 4, nx + (size_t)c * S + q);
            }
            cp_commit();
        }

        // ---- MMA: A streamed from global (L1-hot), B = Xh via ldsm ----
        float d[2][5][4];
        #pragma unroll
        for (int mt = 0; mt < 2; mt++)
            #pragma unroll
            for (int n = 0; n < 5; n++)
                #pragma unroll
                for (int i = 0; i < 4; i++) d[mt][n][i] = 0.0f;

        #pragma unroll
        for (int ks = 0; ks < 8; ks++) {
            uint4 ah0 = __ldg(wh + ((2 * jg)     * 8 + ks) * 32 + lane);
            uint4 ah1 = __ldg(wh + ((2 * jg + 1) * 8 + ks) * 32 + lane);
            uint32_t bh[10];
            ldsm4t(bh,     aXh + ks * KSTEP);
            ldsm4t(bh + 4, aXh + ks * KSTEP + 32);
            ldsm2t(bh + 8, aXh + ks * KSTEP + 64);
            #pragma unroll
            for (int n = 0; n < 5; n++) {
                mma16816(d[0][n], ah0, bh[2 * n], bh[2 * n + 1]);
                mma16816(d[1][n], ah1, bh[2 * n], bh[2 * n + 1]);
            }
        }

        // ---- epilogue: +bias, LN stats over 32 j in-warp + 4-group combine ----
        float sum[5][2], sq[5][2];
        #pragma unroll
        for (int n = 0; n < 5; n++)
            #pragma unroll
            for (int p = 0; p < 2; p++) { sum[n][p] = 0.f; sq[n][p] = 0.f; }

        #pragma unroll
        for (int mt = 0; mt < 2; mt++) {
            int j0 = jg * 32 + mt * 16 + g;
            float b0 = sbp[j0], b1 = sbp[j0 + 8];
            #pragma unroll
            for (int n = 0; n < 5; n++) {
                d[mt][n][0] += b0;
                d[mt][n][1] += b0;
                d[mt][n][2] += b1;
                d[mt][n][3] += b1;
                sum[n][0] += d[mt][n][0] + d[mt][n][2];
                sum[n][1] += d[mt][n][1] + d[mt][n][3];
                sq[n][0] = fmaf(d[mt][n][0], d[mt][n][0],
                           fmaf(d[mt][n][2], d[mt][n][2], sq[n][0]));
                sq[n][1] = fmaf(d[mt][n][1], d[mt][n][1],
                           fmaf(d[mt][n][3], d[mt][n][3], sq[n][1]));
            }
        }
        #pragma unroll
        for (int off = 4; off <= 16; off <<= 1) {
            #pragma unroll
            for (int n = 0; n < 5; n++) {
                #pragma unroll
                for (int p = 0; p < 2; p++) {
                    sum[n][p] += __shfl_xor_sync(0xffffffffu, sum[n][p], off);
                    sq[n][p]  += __shfl_xor_sync(0xffffffffu, sq[n][p],  off);
                }
            }
        }
        if (lane < 4) {
            #pragma unroll
            for (int n = 0; n < 5; n++)
                #pragma unroll
                for (int p = 0; p < 2; p++)
                    red[jg * TS + sb + n * 8 + 2 * lane + p] =
                        make_float2(sum[n][p], sq[n][p]);
        }
        __syncthreads();

        float mu[5][2], rs[5][2];
        #pragma unroll
        for (int n = 0; n < 5; n++) {
            #pragma unroll
            for (int p = 0; p < 2; p++) {
                int col = sb + n * 8 + 2 * t4 + p;
                float sv = 0.f, qv = 0.f;
                #pragma unroll
                for (int jj = 0; jj < 4; jj++) {
                    float2 r = red[jj * TS + col];
                    sv += r.x;
                    qv += r.y;
                }
                float m_  = sv * (1.0f / 128.0f);
                float var = qv * (1.0f / 128.0f) - m_ * m_;
                mu[n][p] = m_;
                rs[n][p] = rsqrtf(var + 1e-5f);
            }
        }

        // ---- apply LN + EXACT fp32 residual from this tile's raw buffer ----
        const int tb = t * TS;
        const float* rwt =
            (const float*)(smem + ((t & 1) ? SM_RAW1 : SM_RAW0));
        #pragma unroll
        for (int mt = 0; mt < 2; mt++) {
            int j0 = jg * 32 + mt * 16 + g;
            int j1 = j0 + 8;
            float g0 = sgp[j0], e0 = sbt[j0];
            float g1 = sgp[j1], e1 = sbt[j1];
            #pragma unroll
            for (int n = 0; n < 5; n++) {
                int sl = sb + n * 8 + 2 * t4;
                float2 x0 = *(const float2*)(rwt + j0 * RAWP + sl);
                float2 x1 = *(const float2*)(rwt + j1 * RAWP + sl);
                float2 o0, o1;
                o0.x = (d[mt][n][0] - mu[n][0]) * rs[n][0] * g0 + e0 + x0.x;
                o0.y = (d[mt][n][1] - mu[n][1]) * rs[n][1] * g0 + e0 + x0.y;
                o1.x = (d[mt][n][2] - mu[n][0]) * rs[n][0] * g1 + e1 + x1.x;
                o1.y = (d[mt][n][3] - mu[n][1]) * rs[n][1] * g1 + e1 + x1.y;
                *(float2*)(ob + (size_t)j0 * S + tb + sl) = o0;
                *(float2*)(ob + (size_t)j1 * S + tb + sl) = o1;
            }
        }

        // ---- next tile raw landed; convert into XH ----
        if (t + 1 < NTILES) {
            cp_wait0();
            __syncthreads();      // all ldsm/residual reads of this tile done
            convert_raw(tid,
                (const float*)(smem + (((t + 1) & 1) ? SM_RAW1 : SM_RAW0)),
                xh);
            __syncthreads();
        }
    }
}

extern "C" void kernel_launch(void* const* d_in, const int* in_sizes, int n_in,
                              void* d_out, int out_size) {
    // metadata order: x, Wq, bq, gq, betaq, Wk, bk, gk, betak, Wp, bp, gp, betap
    const float* x     = (const float*)d_in[0];
    const float* Wp    = (const float*)d_in[9];
    const float* bp    = (const float*)d_in[10];
    const float* gp    = (const float*)d_in[11];
    const float* betap = (const float*)d_in[12];
    float* out = (float*)d_out;

    const int BO = in_sizes[0] / (C * S);   // 1024

    cudaFuncSetAttribute(ca_mma, cudaFuncAttributeMaxDynamicSharedMemorySize,
                         SM_TOTAL);

    wprep<<<8, 256>>>(Wp);
    ca_mma<<<BO, THREADS, SM_TOTAL>>>(x, bp, gp, betap, out);
}

// round 12
// speedup vs baseline: 1.6537x; 1.0591x over previous
#include <cuda_runtime.h>
#include <cuda_fp16.h>
#include <cstdint>

// channel_attention collapses to: out = LN_c(Wp @ x + bp)*gp + betap + x
// (softmax row-sum == 1 makes the q/k/attention branch an identity).
//
// HMMA m16n8k16 fp16 GEMM (y = Wh*Xh; rel_err ~2.5e-4 incl. fp16 residual).
// X path: LDG float4 -> fp16 in registers -> STS (no raw fp32 staging, no
// cp.async round trip). XH double-buffered. Residual read from fp16 XH.
// 8 warps = 4 j-groups x 2 s-halves; A fragments streamed from an L1-hot
// pre-packed global image. ~58 KB smem, 2 CTAs/SM.

#define C        128
#define S        400
#define TS       80
#define NTILES   5
#define THREADS  256
#define XPITCH   88                     // fp16 pitch (halves)
#define KSTEP    (16 * XPITCH * 2)

#define SM_XH0   0                      // 128*88*2 = 22528
#define SM_XH1   32768                  // power-of-2 offset (XOR toggle)
#define SM_BP    55296
#define SM_GP    (SM_BP + 512)
#define SM_BT    (SM_GP + 512)
#define SM_RED   (SM_BT + 512)          // float2[4][80] = 2560
#define SM_TOTAL (SM_RED + 2560)        // 59392 B

// Wh fragments in mma order: [mt 8][ks 8][lane 32] x uint4 (16 KB, L1-hot)
__device__ __align__(16) uint32_t Whf[8 * 8 * 32 * 4];

__device__ __forceinline__ uint32_t smem_u32(const void* p) {
    uint32_t a;
    asm("{ .reg .u64 t; cvta.to.shared.u64 t, %1; cvt.u32.u64 %0, t; }"
        : "=r"(a) : "l"(p));
    return a;
}
__device__ __forceinline__ void ldsm4t(uint32_t* r, uint32_t addr) {
    asm volatile("ldmatrix.sync.aligned.m8n8.x4.trans.shared.b16 {%0,%1,%2,%3}, [%4];"
                 : "=r"(r[0]), "=r"(r[1]), "=r"(r[2]), "=r"(r[3]) : "r"(addr));
}
__device__ __forceinline__ void ldsm2t(uint32_t* r, uint32_t addr) {
    asm volatile("ldmatrix.sync.aligned.m8n8.x2.trans.shared.b16 {%0,%1}, [%2];"
                 : "=r"(r[0]), "=r"(r[1]) : "r"(addr));
}
__device__ __forceinline__ void mma16816(float d[4], uint4 a,
                                         uint32_t b0, uint32_t b1) {
    asm volatile(
        "mma.sync.aligned.m16n8k16.row.col.f32.f16.f16.f32 "
        "{%0,%1,%2,%3}, {%4,%5,%6,%7}, {%8,%9}, {%0,%1,%2,%3};"
        : "+f"(d[0]), "+f"(d[1]), "+f"(d[2]), "+f"(d[3])
        : "r"(a.x), "r"(a.y), "r"(a.z), "r"(a.w), "r"(b0), "r"(b1));
}
__device__ __forceinline__ uint32_t pk_h2(float a, float b) {
    __half2 h = __floats2half2_rn(a, b);    // low = a
    return *reinterpret_cast<uint32_t*>(&h);
}

// pack Wh into mma A-fragment order (mt = 16-j tile index 0..7)
__global__ void wprep(const float* __restrict__ Wp) {
    int idx  = blockIdx.x * 256 + threadIdx.x;   // (mt*8+ks)*32+lane
    int lane = idx & 31;
    int ks   = (idx >> 5) & 7;
    int mt   = idx >> 8;
    uint32_t h4[4];
    #pragma unroll
    for (int r = 0; r < 4; r++) {
        int j = mt * 16 + (r & 1) * 8 + (lane >> 2);
        int c = ks * 16 + (r >> 1) * 8 + 2 * (lane & 3);
        h4[r] = pk_h2(Wp[j * C + c], Wp[j * C + c + 1]);
    }
    ((uint4*)Whf)[idx] = make_uint4(h4[0], h4[1], h4[2], h4[3]);
}

extern __shared__ char smem[];

// load one 80-s tile slice into fp16 register chunks (10 x uint2 / thread)
__device__ __forceinline__ void load_pre(uint2 pre[10], int tid,
                                         const float* __restrict__ xt) {
    #pragma unroll
    for (int k = 0; k < 10; k++) {
        int idx = tid + k * THREADS;
        int c = idx / 20;
        int q = (idx % 20) * 4;
        float4 v = __ldg((const float4*)(xt + (size_t)c * S + q));
        pre[k] = make_uint2(pk_h2(v.x, v.y), pk_h2(v.z, v.w));
    }
}

__global__ __launch_bounds__(THREADS, 2)
void ca_mma(const float* __restrict__ x,
            const float* __restrict__ bp,
            const float* __restrict__ gp,
            const float* __restrict__ betap,
            float* __restrict__ out) {
    const int tid  = threadIdx.x;
    const int warp = tid >> 5;
    const int lane = tid & 31;
    const int jg   = warp >> 1;          // 0..3 : 32-j group
    const int sh   = warp & 1;           // 0..1 : 40-s half
    const int g    = lane >> 2;
    const int t4   = lane & 3;
    const int bo   = blockIdx.x;

    const float* xg = x   + (size_t)bo * C * S;
    float*       ob = out + (size_t)bo * C * S;

    float*  sbp = (float*)(smem + SM_BP);
    float*  sgp = (float*)(smem + SM_GP);
    float*  sbt = (float*)(smem + SM_BT);
    float2* red = (float2*)(smem + SM_RED);

    if (tid < C) {
        sbp[tid] = bp[tid];
        sgp[tid] = gp[tid];
        sbt[tid] = betap[tid];
    }

    const int lr = lane & 15;
    const int lc = (lane >> 4) << 3;
    const int sb = sh * 40;
    const uint32_t s0   = smem_u32(smem);
    const uint32_t xrel = (uint32_t)((lr * XPITCH + sb + lc) * 2);
    const uint4* wh = (const uint4*)Whf;

    // prefetch+convert tile 0 into registers
    uint2 pre[10];
    load_pre(pre, tid, xg);

    for (int t = 0; t < NTILES; t++) {
        const uint32_t xhb = (t & 1) ? SM_XH1 : SM_XH0;
        __half* xh = (__half*)(smem + xhb);

        __syncthreads();   // XH(t&1) readers (tile t-2) are done
        // store converted tile, then issue next tile's loads
        #pragma unroll
        for (int k = 0; k < 10; k++) {
            int idx = tid + k * THREADS;
            int c = idx / 20;
            int q = (idx % 20) * 4;
            *(uint2*)(xh + c * XPITCH + q) = pre[k];
        }
        if (t + 1 < NTILES)
            load_pre(pre, tid, xg + (t + 1) * TS);
        __syncthreads();

        // ---- MMA: A streamed from global (L1-hot), B via ldsm ----
        const uint32_t aXh = s0 + xhb + xrel;
        float d[2][5][4];
        #pragma unroll
        for (int mt = 0; mt < 2; mt++)
            #pragma unroll
            for (int n = 0; n < 5; n++)
                #pragma unroll
                for (int i = 0; i < 4; i++) d[mt][n][i] = 0.0f;

        #pragma unroll
        for (int ks = 0; ks < 8; ks++) {
            uint4 ah0 = __ldg(wh + ((2 * jg)     * 8 + ks) * 32 + lane);
            uint4 ah1 = __ldg(wh + ((2 * jg + 1) * 8 + ks) * 32 + lane);
            uint32_t bh[10];
            ldsm4t(bh,     aXh + ks * KSTEP);
            ldsm4t(bh + 4, aXh + ks * KSTEP + 32);
            ldsm2t(bh + 8, aXh + ks * KSTEP + 64);
            #pragma unroll
            for (int n = 0; n < 5; n++) {
                mma16816(d[0][n], ah0, bh[2 * n], bh[2 * n + 1]);
                mma16816(d[1][n], ah1, bh[2 * n], bh[2 * n + 1]);
            }
        }

        // ---- epilogue: +bias, LN stats over 32 j in-warp + 4-group combine ----
        float sum[5][2], sq[5][2];
        #pragma unroll
        for (int n = 0; n < 5; n++)
            #pragma unroll
            for (int p = 0; p < 2; p++) { sum[n][p] = 0.f; sq[n][p] = 0.f; }

        #pragma unroll
        for (int mt = 0; mt < 2; mt++) {
            int j0 = jg * 32 + mt * 16 + g;
            float b0 = sbp[j0], b1 = sbp[j0 + 8];
            #pragma unroll
            for (int n = 0; n < 5; n++) {
                d[mt][n][0] += b0;
                d[mt][n][1] += b0;
                d[mt][n][2] += b1;
                d[mt][n][3] += b1;
                sum[n][0] += d[mt][n][0] + d[mt][n][2];
                sum[n][1] += d[mt][n][1] + d[mt][n][3];
                sq[n][0] = fmaf(d[mt][n][0], d[mt][n][0],
                           fmaf(d[mt][n][2], d[mt][n][2], sq[n][0]));
                sq[n][1] = fmaf(d[mt][n][1], d[mt][n][1],
                           fmaf(d[mt][n][3], d[mt][n][3], sq[n][1]));
            }
        }
        #pragma unroll
        for (int off = 4; off <= 16; off <<= 1) {
            #pragma unroll
            for (int n = 0; n < 5; n++) {
                #pragma unroll
                for (int p = 0; p < 2; p++) {
                    sum[n][p] += __shfl_xor_sync(0xffffffffu, sum[n][p], off);
                    sq[n][p]  += __shfl_xor_sync(0xffffffffu, sq[n][p],  off);
                }
            }
        }
        if (lane < 4) {
            #pragma unroll
            for (int n = 0; n < 5; n++)
                #pragma unroll
                for (int p = 0; p < 2; p++)
                    red[jg * TS + sb + n * 8 + 2 * lane + p] =
                        make_float2(sum[n][p], sq[n][p]);
        }
        __syncthreads();

        float mu[5][2], rs[5][2];
        #pragma unroll
        for (int n = 0; n < 5; n++) {
            #pragma unroll
            for (int p = 0; p < 2; p++) {
                int col = sb + n * 8 + 2 * t4 + p;
                float sv = 0.f, qv = 0.f;
                #pragma unroll
                for (int jj = 0; jj < 4; jj++) {
                    float2 r = red[jj * TS + col];
                    sv += r.x;
                    qv += r.y;
                }
                float m_  = sv * (1.0f / 128.0f);
                float var = qv * (1.0f / 128.0f) - m_ * m_;
                mu[n][p] = m_;
                rs[n][p] = rsqrtf(var + 1e-5f);
            }
        }

        // ---- apply LN + residual (x from fp16 tile), store ----
        const int tb = t * TS;
        #pragma unroll
        for (int mt = 0; mt < 2; mt++) {
            int j0 = jg * 32 + mt * 16 + g;
            int j1 = j0 + 8;
            float g0 = sgp[j0], e0 = sbt[j0];
            float g1 = sgp[j1], e1 = sbt[j1];
            #pragma unroll
            for (int n = 0; n < 5; n++) {
                int sl = sb + n * 8 + 2 * t4;
                __half2 x0 = *(__half2*)(xh + j0 * XPITCH + sl);
                __half2 x1 = *(__half2*)(xh + j1 * XPITCH + sl);
                float2 o0, o1;
                o0.x = (d[mt][n][0] - mu[n][0]) * rs[n][0] * g0 + e0 +
                       __half2float(x0.x);
                o0.y = (d[mt][n][1] - mu[n][1]) * rs[n][1] * g0 + e0 +
                       __half2float(x0.y);
                o1.x = (d[mt][n][2] - mu[n][0]) * rs[n][0] * g1 + e1 +
                       __half2float(x1.x);
                o1.y = (d[mt][n][3] - mu[n][1]) * rs[n][1] * g1 + e1 +
                       __half2float(x1.y);
                *(float2*)(ob + (size_t)j0 * S + tb + sl) = o0;
                *(float2*)(ob + (size_t)j1 * S + tb + sl) = o1;
            }
        }
    }
}

extern "C" void kernel_launch(void* const* d_in, const int* in_sizes, int n_in,
                              void* d_out, int out_size) {
    // metadata order: x, Wq, bq, gq, betaq, Wk, bk, gk, betak, Wp, bp, gp, betap
    const float* x     = (const float*)d_in[0];
    const float* Wp    = (const float*)d_in[9];
    const float* bp    = (const float*)d_in[10];
    const float* gp    = (const float*)d_in[11];
    const float* betap = (const float*)d_in[12];
    float* out = (float*)d_out;

    const int BO = in_sizes[0] / (C * S);   // 1024

    cudaFuncSetAttribute(ca_mma, cudaFuncAttributeMaxDynamicSharedMemorySize,
                         SM_TOTAL);

    wprep<<<8, 256>>>(Wp);
    ca_mma<<<BO, THREADS, SM_TOTAL>>>(x, bp, gp, betap, out);
}